// round 16
// baseline (speedup 1.0000x reference)
#include <cuda_runtime.h>
#include <cstdint>

// Pooling_38706245271888 — GB300 sm_103a
//   word_vectors [B,T,D] f32; rep_ids/lengths [B,S] i32; masks [B,S] i32
// Output: concat([rep_vec, mean_vec], axis=1) -> [B, 2S, D] f32 (+ mask tail).
#define PB 16
#define PT 4096
#define PD 768
#define PS 64
#define NTHR 192          // 192*4 == 768: thread i owns float4 at dim 4*i
#define BATCH 8           // ping-pong batch: 8 rows in flight while 8 consumed

// Structure change vs R13/R15: ptxas pinned regs at 40 for every unroll depth
// (bursty ~4-5 outstanding loads/thread). Here a MANUAL ping-pong double
// buffer (A/B of 8 rows each, ~64 data regs live) forces ~8 loads
// continuously in flight per thread. Occ drops to 4 CTAs/SM -> 1024 CTAs run
// in ~1.7 waves, so the single-wave CTA-finish spread (the suspected cause of
// the 76% DRAM plateau) is smoothed by work-stealing.
#define ACC(vv)                                                     \
    do {                                                            \
        sum.x += (vv).x; sum.y += (vv).y;                           \
        sum.z += (vv).z; sum.w += (vv).w;                           \
        cnt.x += ((vv).x != 0.f) ? 1.f : 0.f;                       \
        cnt.y += ((vv).y != 0.f) ? 1.f : 0.f;                       \
        cnt.z += ((vv).z != 0.f) ? 1.f : 0.f;                       \
        cnt.w += ((vv).w != 0.f) ? 1.f : 0.f;                       \
    } while (0)

__global__ __launch_bounds__(NTHR, 4) void pool_kernel(
    const float* __restrict__ wv,
    const int* __restrict__ rep_ids,
    const int* __restrict__ rep_mask,
    const int* __restrict__ lengths,
    const int* __restrict__ len_mask,
    float* __restrict__ out,
    int write_mask_tail)
{
    const int blk = blockIdx.x;          // 0 .. B*S-1
    const int b = blk / PS;
    const int j = blk % PS;
    const int tid = threadIdx.x;         // 0 .. 191
    const int d4 = tid * 4;

    // --- sentence span via warp-parallel masked reduce over lengths ---
    __shared__ int s_len[PS];
    __shared__ int s_span[2];
    if (tid < PS) s_len[tid] = lengths[b * PS + tid];
    __syncthreads();
    if (tid < 32) {
        int c = ((tid      < j) ? s_len[tid]      : 0)
              + ((tid + 32 < j) ? s_len[tid + 32] : 0);
        #pragma unroll
        for (int o = 16; o > 0; o >>= 1) c += __shfl_down_sync(0xffffffffu, c, o);
        if (tid == 0) {
            int start = c;
            int end = start + s_len[j];
            if (start > PT) start = PT;  // overflow bucket dropped
            if (end   > PT) end   = PT;
            if (end < start) end = start;
            s_span[0] = start;
            s_span[1] = end;
        }
    }
    __syncthreads();
    const int start = s_span[0];
    const int end   = s_span[1];
    const int n     = end - start;

    const float* __restrict__ base = wv + (size_t)b * PT * PD;

    float4 sum = make_float4(0.f, 0.f, 0.f, 0.f);
    float4 cnt = make_float4(0.f, 0.f, 0.f, 0.f);

    const float* p = base + (size_t)start * PD + d4;
    int t = 0;

    if (n >= 2 * BATCH && (n % (2 * BATCH)) == 0) {
        // --- ping-pong main path (L=64 on this dataset: 4 iterations) ---
        float4 A[BATCH], B[BATCH];
        #pragma unroll
        for (int k = 0; k < BATCH; k++)
            A[k] = __ldcs((const float4*)(p + (size_t)k * PD));

        const int iters = n / (2 * BATCH);
        for (int i = 0; i < iters; i++) {
            // issue B's 8 loads, then consume A while B is in flight
            #pragma unroll
            for (int k = 0; k < BATCH; k++)
                B[k] = __ldcs((const float4*)(p + (size_t)(BATCH + k) * PD));
            #pragma unroll
            for (int k = 0; k < BATCH; k++) ACC(A[k]);

            // issue next A (if any), then consume B
            if (i + 1 < iters) {
                #pragma unroll
                for (int k = 0; k < BATCH; k++)
                    A[k] = __ldcs((const float4*)(p + (size_t)(2 * BATCH + k) * PD));
            }
            #pragma unroll
            for (int k = 0; k < BATCH; k++) ACC(B[k]);

            p += (size_t)(2 * BATCH) * PD;
        }
        t = n;
    }
    // --- generic fallback / remainder (not hit on this dataset) ---
    for (; t + 4 <= n; t += 4, p += 4 * PD) {
        float4 v0 = __ldcs((const float4*)(p));
        float4 v1 = __ldcs((const float4*)(p + PD));
        float4 v2 = __ldcs((const float4*)(p + 2 * PD));
        float4 v3 = __ldcs((const float4*)(p + 3 * PD));
        ACC(v0); ACC(v1); ACC(v2); ACC(v3);
    }
    for (; t < n; t++, p += PD) {
        float4 v = __ldcs((const float4*)(p));
        ACC(v);
    }

    // --- rep gather issued BEFORE the reduce barrier (latency overlap) ---
    int id = rep_ids[b * PS + j];
    if (id < 0) id = 0;
    if (id >= PT) id = PT - 1;
    float4 rv = *(const float4*)(base + (size_t)id * PD + d4);

    // --- block reduce total count (empty-segment fallback detection) ---
    __shared__ float red[256];
    red[tid] = cnt.x + cnt.y + cnt.z + cnt.w;
    if (tid < 64) red[192 + tid] = 0.f;
    __syncthreads();
    for (int off = 128; off > 0; off >>= 1) {
        if (tid < off) red[tid] += red[tid + off];
        __syncthreads();
    }
    const bool empty = (red[0] == 0.f);

    const float lm = len_mask[b * PS + j] ? 1.f : 0.f;
    const float rm = rep_mask[b * PS + j] ? 1.f : 0.f;

    // --- mean vector (divide by per-dim nonzero count, min 1) ---
    float4 mv;
    if (empty) {
        mv = *(const float4*)(wv + d4);   // fallback: word_vectors[0, 0, :]
    } else {
        mv.x = sum.x / ((cnt.x == 0.f) ? 1.f : cnt.x);
        mv.y = sum.y / ((cnt.y == 0.f) ? 1.f : cnt.y);
        mv.z = sum.z / ((cnt.z == 0.f) ? 1.f : cnt.z);
        mv.w = sum.w / ((cnt.w == 0.f) ? 1.f : cnt.w);
    }
    mv.x *= lm; mv.y *= lm; mv.z *= lm; mv.w *= lm;
    rv.x *= rm; rv.y *= rm; rv.z *= rm; rv.w *= rm;

    // --- write: out[b, 0:S, :] = rep, out[b, S:2S, :] = mean ---
    float* orow_rep  = out + ((size_t)b * 2 * PS + j) * PD + d4;
    float* orow_mean = out + ((size_t)b * 2 * PS + PS + j) * PD + d4;
    *(float4*)orow_rep  = rv;
    *(float4*)orow_mean = mv;

    // --- mask tail (output_mask), if the harness buffer includes it ---
    if (write_mask_tail && tid == 0) {
        float* mt = out + (size_t)PB * 2 * PS * PD;
        mt[b * 2 * PS + j]      = rm;
        mt[b * 2 * PS + PS + j] = lm;
    }
}

extern "C" void kernel_launch(void* const* d_in, const int* in_sizes, int n_in,
                              void* d_out, int out_size) {
    const float* wv       = (const float*)d_in[0];
    const int*   rep_ids  = (const int*)d_in[1];
    const int*   rep_mask = (const int*)d_in[2];
    const int*   lengths  = (const int*)d_in[3];
    const int*   len_mask = (const int*)d_in[4];
    float* out = (float*)d_out;

    const int vec_elems  = PB * 2 * PS * PD;   // 1,572,864
    const int mask_elems = PB * 2 * PS;        // 2,048
    int write_mask_tail = (out_size >= vec_elems + mask_elems) ? 1 : 0;

    pool_kernel<<<PB * PS, NTHR>>>(wv, rep_ids, rep_mask, lengths, len_mask,
                                   out, write_mask_tail);
}